// round 10
// baseline (speedup 1.0000x reference)
#include <cuda_runtime.h>
#include <cstddef>

// Depthwise 4x4 FIR conv, stride-2 downsample, zero pad (1,1,1,1).
// x: (16,512,64,64) f32 -> out: (16,512,32,32) f32.
//
// R10: endless rolling pipeline. 4-slot register ring, prefetch distance 3,
// rolling ACROSS planes: each thread handles 4 planes (2 pairs of 2); while
// consuming the last rows of a pair it prefetches the first rows of the next.
// In-flight LDG depth == 3 on every iteration (R8's per-plane pipeline decayed
// 3->0 over the second half of each plane; avg 2.0). Rank-1 weight
// factorization (exact: make_resample_kernel is an outer product) keeps the
// live set at ~62 regs -> 64-reg budget, 4 CTAs x 256 thr = 32 warps/SM.

#define IN_W 64
#define OUT_W 32

__device__ __forceinline__ void consume_row(
    float4 a, float4 bb, bool zero_row, int c,
    const float* __restrict__ u, const float* __restrict__ v, int j,
    float* __restrict__ acc0, float* __restrict__ acc1)
{
    if (zero_row) {
        a  = make_float4(0.f, 0.f, 0.f, 0.f);
        bb = a;
    }
    float vl = __shfl_up_sync(0xffffffffu, bb.w, 1, 8);   // col 8c-1
    float vr = __shfl_down_sync(0xffffffffu, a.x, 1, 8);  // col 8c+8
    if (c == 0) vl = 0.f;
    if (c == 7) vr = 0.f;

    float val[10];
    val[0] = vl;
    val[1] = a.x;  val[2] = a.y;  val[3] = a.z;  val[4] = a.w;
    val[5] = bb.x; val[6] = bb.y; val[7] = bb.z; val[8] = bb.w;
    val[9] = vr;

    float h0 = 0.f, h1 = 0.f, h2 = 0.f, h3 = 0.f;
    #pragma unroll
    for (int t = 0; t < 4; t++) {
        h0 = fmaf(val[0 + t], v[t], h0);
        h1 = fmaf(val[2 + t], v[t], h1);
        h2 = fmaf(val[4 + t], v[t], h2);
        h3 = fmaf(val[6 + t], v[t], h3);
    }
    if (j < 4) {           // tap j for output row 2b
        const float uj = u[j];
        acc0[0] = fmaf(h0, uj, acc0[0]);
        acc0[1] = fmaf(h1, uj, acc0[1]);
        acc0[2] = fmaf(h2, uj, acc0[2]);
        acc0[3] = fmaf(h3, uj, acc0[3]);
    }
    if (j >= 2) {          // tap j-2 for output row 2b+1
        const float uj = u[j - 2];
        acc1[0] = fmaf(h0, uj, acc1[0]);
        acc1[1] = fmaf(h1, uj, acc1[1]);
        acc1[2] = fmaf(h2, uj, acc1[2]);
        acc1[3] = fmaf(h3, uj, acc1[3]);
    }
}

// ---------------- R10: persistent cross-plane rolling pipeline ----------------
// Requires n_planes % (4*gridDim.x) == 0 (each thread: even # of plane-pairs).
__global__ __launch_bounds__(256, 4)
void upfirdn_down2_pipe(const float* __restrict__ x,
                        const float* __restrict__ k,
                        float* __restrict__ out,
                        int n_planes)
{
    const int tid = threadIdx.x;
    const int c   = tid & 7;
    const int b   = (tid >> 3) & 15;
    const int pl  = tid >> 7;

    // Rank-1 factorization of the flipped 4x4.
    const float rk00 = 1.0f / __ldg(&k[0]);
    float u[4], v[4];
    #pragma unroll
    for (int t = 0; t < 4; t++) {
        v[t] = __ldg(&k[3 - t]);
        u[t] = __ldg(&k[(3 - t) * 4]) * rk00;
    }

    int ro[6];
    #pragma unroll
    for (int j = 0; j < 6; j++) {
        int r = 4 * b - 1 + j;
        ro[j] = min(max(r, 0), IN_W - 1) * (IN_W / 4) + c * 2;
    }

    const float4* __restrict__ x4 = (const float4*)x;
    const int PSZ   = IN_W * IN_W / 4;          // 1024 float4 / input plane
    const int obase = (2 * b) * OUT_W + c * 4;
    const int step  = 2 * gridDim.x;            // plane stride per thread
    const int pairs = n_planes / (2 * step);    // plane-pairs per thread

    int p = blockIdx.x * 2 + pl;                // first plane for this thread

    // 4-slot ring: slot t&3 holds stream position t (position = pair*12 + i).
    float4 SA[4], SB[4];
    {   // Prologue: positions 0,1,2 = rows 0..2 of first plane.
        const float4* b0 = x4 + (size_t)p * PSZ;
        SA[0] = __ldg(b0 + ro[0]); SB[0] = __ldg(b0 + ro[0] + 1);
        SA[1] = __ldg(b0 + ro[1]); SB[1] = __ldg(b0 + ro[1] + 1);
        SA[2] = __ldg(b0 + ro[2]); SB[2] = __ldg(b0 + ro[2] + 1);
    }

    for (int pr = 0; pr < pairs; pr++) {
        const int q0 = p;
        const int q1 = p + step;
        const int qn = min(q1 + step, n_planes - 1);   // next pair's q0 (clamped)
        const float4* __restrict__ b0 = x4 + (size_t)q0 * PSZ;
        const float4* __restrict__ b1 = x4 + (size_t)q1 * PSZ;
        const float4* __restrict__ bn = x4 + (size_t)qn * PSZ;

        float acc0[4] = {0.f, 0.f, 0.f, 0.f};
        float acc1[4] = {0.f, 0.f, 0.f, 0.f};

        #pragma unroll
        for (int i = 0; i < 12; i++) {
            // Prefetch stream position i+3 into slot (i+3)&3 (never the slot
            // being consumed this iteration: distance 3 mod 4 != 0).
            {
                const int tp   = i + 3;
                const int prow = (tp < 6) ? tp : (tp < 12) ? tp - 6 : tp - 12;
                const float4* pb = (tp < 6) ? b0 : (tp < 12) ? b1 : bn;
                const int ps = tp & 3;
                SA[ps] = __ldg(pb + ro[prow]);
                SB[ps] = __ldg(pb + ro[prow] + 1);
            }
            // Consume stream position i: plane q0 rows 0..5, then q1 rows 0..5.
            const int j = (i < 6) ? i : i - 6;
            const int s = i & 3;
            const bool zr = (j == 0 && b == 0) || (j == 5 && b == 15);
            consume_row(SA[s], SB[s], zr, c, u, v, j, acc0, acc1);

            if (i == 5) {   // plane q0 complete
                float* o = out + (size_t)q0 * (OUT_W * OUT_W) + obase;
                __stcs((float4*)o,           make_float4(acc0[0], acc0[1], acc0[2], acc0[3]));
                __stcs((float4*)(o + OUT_W), make_float4(acc1[0], acc1[1], acc1[2], acc1[3]));
                #pragma unroll
                for (int q = 0; q < 4; q++) { acc0[q] = 0.f; acc1[q] = 0.f; }
            }
            if (i == 11) {  // plane q1 complete
                float* o = out + (size_t)q1 * (OUT_W * OUT_W) + obase;
                __stcs((float4*)o,           make_float4(acc0[0], acc0[1], acc0[2], acc0[3]));
                __stcs((float4*)(o + OUT_W), make_float4(acc1[0], acc1[1], acc1[2], acc1[3]));
            }
        }
        p += 2 * step;
    }
}

// ---------------- Fallback: R8 kernel (best known non-persistent) -------------
__global__ __launch_bounds__(256, 4)
void upfirdn_down2_r8(const float* __restrict__ x,
                      const float* __restrict__ k,
                      float* __restrict__ out,
                      int n_planes)
{
    const int tid = threadIdx.x;
    const int c   = tid & 7;
    const int b   = (tid >> 3) & 15;
    const int pl  = tid >> 7;
    const int plane = blockIdx.x * 2 + pl;
    if (plane >= n_planes) return;

    const float rk00 = 1.0f / __ldg(&k[0]);
    float u[4], v[4];
    #pragma unroll
    for (int t = 0; t < 4; t++) {
        v[t] = __ldg(&k[3 - t]);
        u[t] = __ldg(&k[(3 - t) * 4]) * rk00;
    }

    const float4* __restrict__ xin =
        (const float4*)(x + (size_t)plane * (IN_W * IN_W));

    int ro[6];
    #pragma unroll
    for (int j = 0; j < 6; j++) {
        int r = 4 * b - 1 + j;
        ro[j] = min(max(r, 0), IN_W - 1) * (IN_W / 4) + c * 2;
    }

    float4 A[6], B[6];
    #pragma unroll
    for (int j = 0; j < 3; j++) { A[j] = __ldg(xin + ro[j]); B[j] = __ldg(xin + ro[j] + 1); }

    float acc0[4] = {0.f, 0.f, 0.f, 0.f};
    float acc1[4] = {0.f, 0.f, 0.f, 0.f};

    #pragma unroll
    for (int j = 0; j < 6; j++) {
        if (j < 3) { A[j + 3] = __ldg(xin + ro[j + 3]); B[j + 3] = __ldg(xin + ro[j + 3] + 1); }
        const bool zr = (j == 0 && b == 0) || (j == 5 && b == 15);
        consume_row(A[j], B[j], zr, c, u, v, j, acc0, acc1);
    }

    float* o = out + (size_t)plane * (OUT_W * OUT_W) + (2 * b) * OUT_W + c * 4;
    __stcs((float4*)o,           make_float4(acc0[0], acc0[1], acc0[2], acc0[3]));
    __stcs((float4*)(o + OUT_W), make_float4(acc1[0], acc1[1], acc1[2], acc1[3]));
}

extern "C" void kernel_launch(void* const* d_in, const int* in_sizes, int n_in,
                              void* d_out, int out_size)
{
    int xi = 0, ki = 1;
    if (n_in >= 2 && in_sizes[0] < in_sizes[1]) { xi = 1; ki = 0; }

    const float* x = (const float*)d_in[xi];
    const float* k = (const float*)d_in[ki];
    float* out = (float*)d_out;

    const int n_planes = in_sizes[xi] / (IN_W * IN_W);   // 8192

    const int grid_pipe = 1024;                 // 4 planes per thread (2 pairs)
    if (n_planes % (4 * grid_pipe) == 0) {
        upfirdn_down2_pipe<<<grid_pipe, 256>>>(x, k, out, n_planes);
    } else {
        const int blocks = (n_planes + 1) / 2;
        upfirdn_down2_r8<<<blocks, 256>>>(x, k, out, n_planes);
    }
}

// round 11
// speedup vs baseline: 1.3626x; 1.3626x over previous
#include <cuda_runtime.h>
#include <cstddef>

// Depthwise 4x4 FIR conv, stride-2 downsample, zero pad (1,1,1,1).
// x: (16,512,64,64) f32 -> out: (16,512,32,32) f32.
//
// R11 = R8 (best known: ncu 25.15us, DRAM 74.6%) with 128-thread CTAs:
// one plane per CTA, grid = n_planes (8192). Same per-thread code, same
// 64-reg / 32-warps-per-SM machine state (__launch_bounds__(128,8)); finer
// CTA granularity smooths tail waves. R10 lesson: static flat buffers +
// simple addressing beat rolling rings (scoreboard slot-recycle serializes).
//
// Per-thread: 2x4 output block (rows 2b,2b+1; cols 4c..4c+3) from 6 input
// rows x 10 cols; depth-3 rolling prefetch inside the plane. Rank-1 weight
// factorization (exact: make_resample_kernel builds k as an outer product):
// u[i]=k[3-i][0]/k[0][0], v[j]=k[0][3-j] reproduce the flipped 4x4 taps.

#define IN_W 64
#define OUT_W 32

__global__ __launch_bounds__(128, 8)
void upfirdn_down2_kernel(const float* __restrict__ x,
                          const float* __restrict__ k,
                          float* __restrict__ out,
                          int n_planes)
{
    const int tid = threadIdx.x;
    const int c   = tid & 7;          // col group: output cols 4c..4c+3
    const int b   = tid >> 3;         // row block: output rows 2b, 2b+1 (0..15)
    const int plane = blockIdx.x;
    if (plane >= n_planes) return;

    // Rank-1 factorization of the flipped 4x4 (exact for outer-product FIR).
    const float rk00 = 1.0f / __ldg(&k[0]);
    float u[4], v[4];
    #pragma unroll
    for (int t = 0; t < 4; t++) {
        v[t] = __ldg(&k[3 - t]);              // k[0][3-t]
        u[t] = __ldg(&k[(3 - t) * 4]) * rk00; // k[3-t][0] / k[0][0]
    }

    const float4* __restrict__ xin =
        (const float4*)(x + (size_t)plane * (IN_W * IN_W));

    // Clamped row offsets in float4 units (row r = 4b-1+j, j=0..5).
    int ro[6];
    #pragma unroll
    for (int j = 0; j < 6; j++) {
        int r = 4 * b - 1 + j;
        ro[j] = min(max(r, 0), IN_W - 1) * (IN_W / 4) + c * 2;
    }

    float4 A[6], B[6];
    // Prologue: rows 0..2 in flight (depth-3 pipeline).
    #pragma unroll
    for (int j = 0; j < 3; j++) { A[j] = __ldg(xin + ro[j]); B[j] = __ldg(xin + ro[j] + 1); }

    float acc0[4] = {0.f, 0.f, 0.f, 0.f};
    float acc1[4] = {0.f, 0.f, 0.f, 0.f};

    #pragma unroll
    for (int j = 0; j < 6; j++) {
        // Keep the pipe fed: issue row j+3 before consuming row j.
        if (j < 3) { A[j + 3] = __ldg(xin + ro[j + 3]); B[j + 3] = __ldg(xin + ro[j + 3] + 1); }

        float4 a  = A[j];
        float4 bb = B[j];
        // Zero the (at most one) out-of-range row. Uniform within the 8-lane
        // segment (same b, same j), so shuffles below stay consistent.
        if ((j == 0 && b == 0) || (j == 5 && b == 15)) {
            a  = make_float4(0.f, 0.f, 0.f, 0.f);
            bb = a;
        }
        float vl = __shfl_up_sync(0xffffffffu, bb.w, 1, 8);   // col 8c-1
        float vr = __shfl_down_sync(0xffffffffu, a.x, 1, 8);  // col 8c+8
        if (c == 0) vl = 0.f;
        if (c == 7) vr = 0.f;

        float val[10];
        val[0] = vl;
        val[1] = a.x;  val[2] = a.y;  val[3] = a.z;  val[4] = a.w;
        val[5] = bb.x; val[6] = bb.y; val[7] = bb.z; val[8] = bb.w;
        val[9] = vr;

        // Horizontal pass: 4 taps -> per-output-col row sums.
        float h0 = 0.f, h1 = 0.f, h2 = 0.f, h3 = 0.f;
        #pragma unroll
        for (int t = 0; t < 4; t++) {
            h0 = fmaf(val[0 + t], v[t], h0);
            h1 = fmaf(val[2 + t], v[t], h1);
            h2 = fmaf(val[4 + t], v[t], h2);
            h3 = fmaf(val[6 + t], v[t], h3);
        }

        // Vertical pass: row j is tap j for out-row 2b (j<4), tap j-2 for 2b+1.
        if (j < 4) {
            const float uj = u[j];
            acc0[0] = fmaf(h0, uj, acc0[0]);
            acc0[1] = fmaf(h1, uj, acc0[1]);
            acc0[2] = fmaf(h2, uj, acc0[2]);
            acc0[3] = fmaf(h3, uj, acc0[3]);
        }
        if (j >= 2) {
            const float uj = u[j - 2];
            acc1[0] = fmaf(h0, uj, acc1[0]);
            acc1[1] = fmaf(h1, uj, acc1[1]);
            acc1[2] = fmaf(h2, uj, acc1[2]);
            acc1[3] = fmaf(h3, uj, acc1[3]);
        }
    }

    float* o = out + (size_t)plane * (OUT_W * OUT_W) + (2 * b) * OUT_W + c * 4;
    __stcs((float4*)o,           make_float4(acc0[0], acc0[1], acc0[2], acc0[3]));
    __stcs((float4*)(o + OUT_W), make_float4(acc1[0], acc1[1], acc1[2], acc1[3]));
}

extern "C" void kernel_launch(void* const* d_in, const int* in_sizes, int n_in,
                              void* d_out, int out_size)
{
    int xi = 0, ki = 1;
    if (n_in >= 2 && in_sizes[0] < in_sizes[1]) { xi = 1; ki = 0; }

    const float* x = (const float*)d_in[xi];
    const float* k = (const float*)d_in[ki];
    float* out = (float*)d_out;

    const int n_planes = in_sizes[xi] / (IN_W * IN_W);   // 8192

    upfirdn_down2_kernel<<<n_planes, 128>>>(x, k, out, n_planes);
}